// round 1
// baseline (speedup 1.0000x reference)
#include <cuda_runtime.h>

#define NPIL   40000
#define NMAX   32
#define BATCH  4
#define XL     432
#define YL     496
#define OC     64
#define OUT_ELEMS (BATCH*OC*YL*XL)   // 54,853,632

// Scratch (allocation-free: __device__ globals)
__device__ float g_xmax[NPIL*OC];
__device__ float g_xmin[NPIL*OC];
__device__ float g_sum[OC];
__device__ float g_sumsq[OC];
__device__ float g_a[OC];
__device__ float g_b[OC];

// ---------------------------------------------------------------------------
// K0: zero the canvas (float4 vectorized) and the BN stat accumulators
// ---------------------------------------------------------------------------
__global__ __launch_bounds__(256) void k_zero(float4* __restrict__ out) {
    unsigned i = blockIdx.x * 256u + threadIdx.x;
    if (i < OUT_ELEMS / 4u) out[i] = make_float4(0.f, 0.f, 0.f, 0.f);
    if (blockIdx.x == 0 && threadIdx.x < OC) {
        g_sum[threadIdx.x]   = 0.f;
        g_sumsq[threadIdx.x] = 0.f;
    }
}

// ---------------------------------------------------------------------------
// K1: per-pillar encode. Block = 256 threads = 4 pillar-groups x 64 channels.
// Computes x[p,o,n] = A_o . q_n + c_{p,o}; tracks per-(p,o) max/min over n
// (with 0-clamp for masked slots) and per-channel sum/sumsq for BN stats.
// ---------------------------------------------------------------------------
__global__ __launch_bounds__(256) void k_encode(const float*  __restrict__ pillars,
                                                const int*    __restrict__ coors,
                                                const int*    __restrict__ npoints,
                                                const float*  __restrict__ W) {
    __shared__ float4 pts[4][NMAX];       // 2 KB  raw points per pillar-group
    __shared__ float  wsh[OC * 9];        // 2.25 KB
    __shared__ float  reds[256], redq[256];

    const int tid = threadIdx.x;
    const int g   = tid >> 6;             // pillar-group in block (0..3)
    const int o   = tid & 63;             // output channel

    // cooperative W load (once per block)
    for (int i = tid; i < OC * 9; i += 256) wsh[i] = W[i];

    // cooperative pillar load: 128 floats per pillar = 64 x float2
    const int p = blockIdx.x * 4 + g;
    const float2* src = (const float2*)(pillars + (size_t)p * NMAX * 4);
    ((float2*)&pts[g][0])[o] = src[o];
    __syncthreads();

    // per-channel collapsed weights
    const float w4 = wsh[o*9+4], w5 = wsh[o*9+5], w6 = wsh[o*9+6],
                w7 = wsh[o*9+7], w8 = wsh[o*9+8];
    const float A0 = wsh[o*9+0] + w4 + w7;
    const float A1 = wsh[o*9+1] + w5 + w8;
    const float A2 = wsh[o*9+2] + w6;
    const float A3 = wsh[o*9+3];

    const int npts = npoints[p];
    const int cxi  = coors[p*3+1];
    const int cyi  = coors[p*3+2];

    // center: reference sums ALL 32 points, divides by npts
    float sx = 0.f, sy = 0.f, sz = 0.f;
    #pragma unroll
    for (int n = 0; n < NMAX; n++) {
        float4 q = pts[g][n];
        sx += q.x; sy += q.y; sz += q.z;
    }
    const float inv = 1.0f / (float)npts;
    const float mx = sx * inv, my = sy * inv, mz = sz * inv;
    const float cvx = (float)cxi * 0.16f + 0.08f;      // VX/2 + pc_range[0]
    const float cvy = (float)cyi * 0.16f + (-39.6f);   // VY/2 + pc_range[1]
    const float c   = -(w4*mx + w5*my + w6*mz + w7*cvx + w8*cvy);

    float xmx = -3.4e38f, xmn = 3.4e38f, ssum = 0.f, ssq = 0.f;
    for (int n = 0; n < npts; n++) {       // uniform per group (npts>=1)
        float4 q = pts[g][n];
        float x = c;
        x = fmaf(A0, q.x, x);
        x = fmaf(A1, q.y, x);
        x = fmaf(A2, q.z, x);
        x = fmaf(A3, q.w, x);
        ssum += x;
        ssq  = fmaf(x, x, ssq);
        xmx  = fmaxf(xmx, x);
        xmn  = fminf(xmn, x);
    }
    if (npts < NMAX) {                     // masked slots contribute exact zeros
        xmx = fmaxf(xmx, 0.f);
        xmn = fminf(xmn, 0.f);
    }
    g_xmax[(size_t)p * OC + o] = xmx;
    g_xmin[(size_t)p * OC + o] = xmn;

    // BN stat reduction: 4 groups -> 64 channels, then one atomic per channel
    reds[tid] = ssum; redq[tid] = ssq;
    __syncthreads();
    if (tid < OC) {
        float ts = reds[tid] + reds[64+tid] + reds[128+tid] + reds[192+tid];
        float tq = redq[tid] + redq[64+tid] + redq[128+tid] + redq[192+tid];
        atomicAdd(&g_sum[tid],   ts);
        atomicAdd(&g_sumsq[tid], tq);
    }
}

// ---------------------------------------------------------------------------
// K2: finalize BN affine coefficients a,b per channel (1 block)
// ---------------------------------------------------------------------------
__global__ void k_bn(const float* __restrict__ gamma, const float* __restrict__ beta) {
    const int o = threadIdx.x;
    const float cnt  = (float)NPIL * (float)NMAX;
    const float mean = g_sum[o] / cnt;
    const float var  = g_sumsq[o] / cnt - mean * mean;
    const float invs = rsqrtf(var + 1e-3f);
    const float a    = gamma[o] * invs;
    g_a[o] = a;
    g_b[o] = beta[o] - mean * a;
}

// ---------------------------------------------------------------------------
// K3: fused BN-apply + ReLU + maxpool + scatter.
// max_n relu(a*x+b) = relu(a*xmax+b) if a>=0 else relu(a*xmin+b)
// ---------------------------------------------------------------------------
__global__ __launch_bounds__(256) void k_scatter(const int* __restrict__ coors,
                                                 float* __restrict__ out) {
    const int tid = threadIdx.x;
    const int p = blockIdx.x * 4 + (tid >> 6);
    const int o = tid & 63;
    const int b  = coors[p*3+0];
    const int xi = coors[p*3+1];
    const int yi = coors[p*3+2];
    const float a  = g_a[o];
    const float bb = g_b[o];
    const float xm = (a >= 0.f) ? g_xmax[(size_t)p * OC + o]
                                : g_xmin[(size_t)p * OC + o];
    const float v = fmaxf(fmaf(a, xm, bb), 0.f);
    out[((((size_t)b * OC + o) * YL) + yi) * XL + xi] = v;
}

// ---------------------------------------------------------------------------
extern "C" void kernel_launch(void* const* d_in, const int* in_sizes, int n_in,
                              void* d_out, int out_size) {
    const float* pillars = (const float*)d_in[0];
    const int*   coors   = (const int*)  d_in[1];
    const int*   npoints = (const int*)  d_in[2];
    const float* W       = (const float*)d_in[3];
    const float* gamma   = (const float*)d_in[4];
    const float* beta    = (const float*)d_in[5];
    float* out = (float*)d_out;

    k_zero<<<(OUT_ELEMS / 4 + 255) / 256, 256>>>((float4*)out);
    k_encode<<<NPIL / 4, 256>>>(pillars, coors, npoints, W);
    k_bn<<<1, OC>>>(gamma, beta);
    k_scatter<<<NPIL / 4, 256>>>(coors, out);
}

// round 3
// speedup vs baseline: 1.2739x; 1.2739x over previous
#include <cuda_runtime.h>

#define NPIL   40000
#define NMAX   32
#define BATCH  4
#define XL     432
#define YL     496
#define OC     64
#define YX     (YL*XL)                 // 214,272
#define OUT_ELEMS (BATCH*OC*YX)        // 54,853,632
#define MAP_ELEMS (BATCH*YX)           // 857,088

// Scratch (allocation-free: __device__ globals)
__device__ float g_xmax[NPIL*OC];
__device__ float g_xmin[NPIL*OC];
__device__ float g_val [NPIL*OC];
__device__ int   g_map [MAP_ELEMS];
__device__ float g_sum[OC];
__device__ float g_sumsq[OC];
__device__ float g_a[OC];
__device__ float g_b[OC];

// ---------------------------------------------------------------------------
// K0: init cell->pillar map to -1; zero BN stat accumulators. (~3.4 MB)
// ---------------------------------------------------------------------------
__global__ __launch_bounds__(256) void k_init() {
    unsigned i = blockIdx.x * 256u + threadIdx.x;
    if (i < MAP_ELEMS / 4u)
        ((int4*)g_map)[i] = make_int4(-1, -1, -1, -1);
    if (blockIdx.x == 0 && threadIdx.x < OC) {
        g_sum[threadIdx.x]   = 0.f;
        g_sumsq[threadIdx.x] = 0.f;
    }
}

// ---------------------------------------------------------------------------
// K1: per-pillar encode. Block = 256 threads = 4 pillar-groups x 64 channels.
// x[p,o,n] = A_o . q_n + c_{p,o}; per-(p,o) max/min over n (0-clamped when
// masked slots exist) + per-channel sum/sumsq for BN. Also scatters pillar id
// into the cell map.
// ---------------------------------------------------------------------------
__global__ __launch_bounds__(256) void k_encode(const float*  __restrict__ pillars,
                                                const int*    __restrict__ coors,
                                                const int*    __restrict__ npoints,
                                                const float*  __restrict__ W) {
    __shared__ float4 pts[4][NMAX];       // 2 KB
    __shared__ float  wsh[OC * 9];        // 2.25 KB
    __shared__ float  reds[256], redq[256];

    const int tid = threadIdx.x;
    const int g   = tid >> 6;             // pillar-group in block (0..3)
    const int o   = tid & 63;             // output channel
    const int lane = tid & 31;

    for (int i = tid; i < OC * 9; i += 256) wsh[i] = W[i];

    const int p = blockIdx.x * 4 + g;
    const float2* src = (const float2*)(pillars + (size_t)p * NMAX * 4);
    ((float2*)&pts[g][0])[o] = src[o];
    __syncthreads();

    const float w4 = wsh[o*9+4], w5 = wsh[o*9+5], w6 = wsh[o*9+6],
                w7 = wsh[o*9+7], w8 = wsh[o*9+8];
    const float A0 = wsh[o*9+0] + w4 + w7;
    const float A1 = wsh[o*9+1] + w5 + w8;
    const float A2 = wsh[o*9+2] + w6;
    const float A3 = wsh[o*9+3];

    const int npts = npoints[p];
    const int bi   = coors[p*3+0];
    const int cxi  = coors[p*3+1];
    const int cyi  = coors[p*3+2];

    if (o == 0)  // one writer per pillar: scatter pillar id into cell map
        g_map[bi * YX + cyi * XL + cxi] = p;

    // center: sum ALL 32 points (matches reference), computed cooperatively:
    // lane l holds point l of this group's pillar; butterfly-reduce over warp.
    {
        float4 q = pts[g][lane];
        float sx = q.x, sy = q.y, sz = q.z;
        #pragma unroll
        for (int off = 16; off; off >>= 1) {
            sx += __shfl_xor_sync(0xffffffffu, sx, off);
            sy += __shfl_xor_sync(0xffffffffu, sy, off);
            sz += __shfl_xor_sync(0xffffffffu, sz, off);
        }
        const float inv = 1.0f / (float)npts;
        const float mx = sx * inv, my = sy * inv, mz = sz * inv;
        const float cvx = (float)cxi * 0.16f + 0.08f;
        const float cvy = (float)cyi * 0.16f + (-39.6f);
        // fallthrough constant via registers:
        float c = -(w4*mx + w5*my + w6*mz + w7*cvx + w8*cvy);

        float xmx = -3.4e38f, xmn = 3.4e38f, ssum = 0.f, ssq = 0.f;
        for (int n = 0; n < npts; n++) {
            float4 q2 = pts[g][n];
            float x = c;
            x = fmaf(A0, q2.x, x);
            x = fmaf(A1, q2.y, x);
            x = fmaf(A2, q2.z, x);
            x = fmaf(A3, q2.w, x);
            ssum += x;
            ssq  = fmaf(x, x, ssq);
            xmx  = fmaxf(xmx, x);
            xmn  = fminf(xmn, x);
        }
        if (npts < NMAX) { xmx = fmaxf(xmx, 0.f); xmn = fminf(xmn, 0.f); }
        g_xmax[(size_t)p * OC + o] = xmx;
        g_xmin[(size_t)p * OC + o] = xmn;

        reds[tid] = ssum; redq[tid] = ssq;
    }
    __syncthreads();
    if (tid < OC) {
        float ts = reds[tid] + reds[64+tid] + reds[128+tid] + reds[192+tid];
        float tq = redq[tid] + redq[64+tid] + redq[128+tid] + redq[192+tid];
        atomicAdd(&g_sum[tid],   ts);
        atomicAdd(&g_sumsq[tid], tq);
    }
}

// ---------------------------------------------------------------------------
// K2: finalize BN affine coefficients (1 block)
// ---------------------------------------------------------------------------
__global__ void k_bn(const float* __restrict__ gamma, const float* __restrict__ beta) {
    const int o = threadIdx.x;
    const float cnt  = (float)NPIL * (float)NMAX;
    const float mean = g_sum[o] / cnt;
    const float var  = g_sumsq[o] / cnt - mean * mean;
    const float a    = gamma[o] * rsqrtf(var + 1e-3f);
    g_a[o] = a;
    g_b[o] = beta[o] - mean * a;
}

// ---------------------------------------------------------------------------
// K3: bake BN+ReLU+maxpool into per-pillar values (coalesced, 30 MB total)
// max_n relu(a*x+b) = relu(a*xmax+b) if a>=0 else relu(a*xmin+b)
// ---------------------------------------------------------------------------
__global__ __launch_bounds__(256) void k_val() {
    const unsigned t  = blockIdx.x * 256u + threadIdx.x;
    const unsigned e0 = t * 4u;                      // NPIL*OC = 2.56M, /4 per thread
    const int o = e0 & 63;
    float4 a  = *(const float4*)&g_a[o];
    float4 bb = *(const float4*)&g_b[o];
    float4 mx = *(const float4*)&g_xmax[e0];
    float4 mn = *(const float4*)&g_xmin[e0];
    float4 v;
    v.x = fmaxf(fmaf(a.x, (a.x >= 0.f ? mx.x : mn.x), bb.x), 0.f);
    v.y = fmaxf(fmaf(a.y, (a.y >= 0.f ? mx.y : mn.y), bb.y), 0.f);
    v.z = fmaxf(fmaf(a.z, (a.z >= 0.f ? mx.z : mn.z), bb.z), 0.f);
    v.w = fmaxf(fmaf(a.w, (a.w >= 0.f ? mx.w : mn.w), bb.w), 0.f);
    *(float4*)&g_val[e0] = v;
}

// ---------------------------------------------------------------------------
// K4: coalesced gather-fill of the whole canvas.
// Thread = 4 x-cells x 4 channels. Reads int4 map (L2-resident, reuse x16),
// gathers float4 per-pillar values at occupied cells, writes 4 coalesced
// float4 stores (one per channel plane).
// ---------------------------------------------------------------------------
__global__ __launch_bounds__(256) void k_fill(float* __restrict__ out) {
    const unsigned t  = blockIdx.x * 256u + threadIdx.x;
    const unsigned xq = t % (XL/4);                  // 108 x-quads
    const unsigned cq = (t / (XL/4)) % (OC/4);       // 16 channel-quads
    const unsigned by = t / ((XL/4) * (OC/4));       // (b,y) pair, 1984 total
    const unsigned b  = by / YL;
    const unsigned y  = by % YL;

    const int4 m = *(const int4*)&g_map[b * YX + y * XL + xq * 4];

    float4 vv0, vv1, vv2, vv3;
    const float4 z = make_float4(0.f, 0.f, 0.f, 0.f);
    vv0 = (m.x >= 0) ? *(const float4*)&g_val[(size_t)m.x * OC + cq*4] : z;
    vv1 = (m.y >= 0) ? *(const float4*)&g_val[(size_t)m.y * OC + cq*4] : z;
    vv2 = (m.z >= 0) ? *(const float4*)&g_val[(size_t)m.z * OC + cq*4] : z;
    vv3 = (m.w >= 0) ? *(const float4*)&g_val[(size_t)m.w * OC + cq*4] : z;

    // 4x4 register transpose: plane i gets component i of each cell
    float4 w0 = make_float4(vv0.x, vv1.x, vv2.x, vv3.x);
    float4 w1 = make_float4(vv0.y, vv1.y, vv2.y, vv3.y);
    float4 w2 = make_float4(vv0.z, vv1.z, vv2.z, vv3.z);
    float4 w3 = make_float4(vv0.w, vv1.w, vv2.w, vv3.w);

    size_t base = (((size_t)b * OC + cq*4) * YL + y) * XL + xq * 4;
    *(float4*)(out + base)            = w0;
    *(float4*)(out + base + (size_t)YX)   = w1;
    *(float4*)(out + base + (size_t)2*YX) = w2;
    *(float4*)(out + base + (size_t)3*YX) = w3;
}

// ---------------------------------------------------------------------------
extern "C" void kernel_launch(void* const* d_in, const int* in_sizes, int n_in,
                              void* d_out, int out_size) {
    const float* pillars = (const float*)d_in[0];
    const int*   coors   = (const int*)  d_in[1];
    const int*   npoints = (const int*)  d_in[2];
    const float* W       = (const float*)d_in[3];
    const float* gamma   = (const float*)d_in[4];
    const float* beta    = (const float*)d_in[5];
    float* out = (float*)d_out;

    k_init  <<<(MAP_ELEMS/4 + 255) / 256, 256>>>();
    k_encode<<<NPIL / 4, 256>>>(pillars, coors, npoints, W);
    k_bn    <<<1, OC>>>(gamma, beta);
    k_val   <<<(NPIL*OC/4) / 256, 256>>>();
    k_fill  <<<(OUT_ELEMS/16) / 256, 256>>>(out);
}

// round 4
// speedup vs baseline: 1.6629x; 1.3054x over previous
#include <cuda_runtime.h>

#define NPIL   40000
#define NMAX   32
#define BATCH  4
#define XL     432
#define YL     496
#define OC     64
#define YX     (YL*XL)                 // 214,272
#define OUT_ELEMS (BATCH*OC*YX)        // 54,853,632
#define MAP_ELEMS (BATCH*YX)           // 857,088

// Scratch (allocation-free: __device__ globals)
// g_mm layout: [p][cq(16)][ mx0..mx3, mn0..mn3 ]  -> 32B per (p, channel-quad)
__device__ float g_mm [NPIL*OC*2];
__device__ int   g_map[MAP_ELEMS];
__device__ float g_sum[OC];
__device__ float g_sumsq[OC];
__device__ float g_a[OC];
__device__ float g_b[OC];

typedef unsigned long long u64;
__device__ __forceinline__ u64 pk2(float lo, float hi) {
    u64 r; asm("mov.b64 %0, {%1,%2};" : "=l"(r) : "f"(lo), "f"(hi)); return r;
}
__device__ __forceinline__ void upk2(float& lo, float& hi, u64 v) {
    asm("mov.b64 {%0,%1}, %2;" : "=f"(lo), "=f"(hi) : "l"(v));
}
#define FMA2(d,a,b,c) asm("fma.rn.f32x2 %0, %1, %2, %3;" : "=l"(d) : "l"(a), "l"(b), "l"(c))
#define ADD2(d,a,b)   asm("add.rn.f32x2 %0, %1, %2;"     : "=l"(d) : "l"(a), "l"(b))

// ---------------------------------------------------------------------------
// K0: init cell->pillar map to -1; zero BN stat accumulators.
// ---------------------------------------------------------------------------
__global__ __launch_bounds__(256) void k_init() {
    unsigned i = blockIdx.x * 256u + threadIdx.x;
    if (i < MAP_ELEMS / 4u)
        ((int4*)g_map)[i] = make_int4(-1, -1, -1, -1);
    if (blockIdx.x == 0 && threadIdx.x < OC) {
        g_sum[threadIdx.x]   = 0.f;
        g_sumsq[threadIdx.x] = 0.f;
    }
}

// ---------------------------------------------------------------------------
// K1: per-pillar encode. Block = 256 threads = 4 pillar-groups x 64 channels.
// Points stored SoA in shared ([comp][n]) so LDS.64 yields packed point-pairs
// for fma.rn.f32x2. Tracks per-(p,o) max/min over n (0-clamped for masked
// slots) + per-channel sum/sumsq for BN. Scatters pillar id into cell map.
// ---------------------------------------------------------------------------
__global__ __launch_bounds__(256) void k_encode(const float*  __restrict__ pillars,
                                                const int*    __restrict__ coors,
                                                const int*    __restrict__ npoints,
                                                const float*  __restrict__ W) {
    __shared__ __align__(16) float pts[4][4][NMAX];   // [group][comp][n], 2 KB
    __shared__ float wsh[OC * 9];                     // 2.25 KB
    __shared__ float reds[256], redq[256];

    const int tid  = threadIdx.x;
    const int g    = tid >> 6;            // pillar-group in block (0..3)
    const int o    = tid & 63;            // output channel
    const int lane = tid & 31;

    for (int i = tid; i < OC * 9; i += 256) wsh[i] = W[i];

    const int p = blockIdx.x * 4 + g;
    // coalesced global read + SoA transpose into shared
    {
        const float2* src = (const float2*)(pillars + (size_t)p * NMAX * 4);
        float2 f = src[o];                // elements e0=2o, e1=2o+1
        int e0 = 2 * o;
        pts[g][e0 & 3][e0 >> 2]       = f.x;
        pts[g][(e0 + 1) & 3][e0 >> 2] = f.y;
    }
    __syncthreads();

    const float w4 = wsh[o*9+4], w5 = wsh[o*9+5], w6 = wsh[o*9+6],
                w7 = wsh[o*9+7], w8 = wsh[o*9+8];
    const float A0 = wsh[o*9+0] + w4 + w7;
    const float A1 = wsh[o*9+1] + w5 + w8;
    const float A2 = wsh[o*9+2] + w6;
    const float A3 = wsh[o*9+3];

    const int npts = npoints[p];
    const int bi   = coors[p*3+0];
    const int cxi  = coors[p*3+1];
    const int cyi  = coors[p*3+2];

    if (o == 0)  // one writer per pillar: scatter pillar id into cell map
        g_map[bi * YX + cyi * XL + cxi] = p;

    // center: sum ALL 32 points (matches reference); lane l holds point l.
    float sx = pts[g][0][lane], sy = pts[g][1][lane], sz = pts[g][2][lane];
    #pragma unroll
    for (int off = 16; off; off >>= 1) {
        sx += __shfl_xor_sync(0xffffffffu, sx, off);
        sy += __shfl_xor_sync(0xffffffffu, sy, off);
        sz += __shfl_xor_sync(0xffffffffu, sz, off);
    }
    const float inv = 1.0f / (float)npts;
    const float mx_ = sx * inv, my_ = sy * inv, mz_ = sz * inv;
    const float cvx = (float)cxi * 0.16f + 0.08f;
    const float cvy = (float)cyi * 0.16f + (-39.6f);
    const float c   = -(w4*mx_ + w5*my_ + w6*mz_ + w7*cvx + w8*cvy);

    const u64 A0p = pk2(A0, A0), A1p = pk2(A1, A1),
              A2p = pk2(A2, A2), A3p = pk2(A3, A3), cp = pk2(c, c);

    float xmx = -3.4e38f, xmn = 3.4e38f;
    u64 ssum2 = 0ull, ssq2 = 0ull;        // packed {0.f, 0.f}
    const int npair = npts & ~1;
    for (int n = 0; n < npair; n += 2) {
        u64 qx = *(const u64*)&pts[g][0][n];
        u64 qy = *(const u64*)&pts[g][1][n];
        u64 qz = *(const u64*)&pts[g][2][n];
        u64 qw = *(const u64*)&pts[g][3][n];
        u64 x = cp;
        FMA2(x, A0p, qx, x);
        FMA2(x, A1p, qy, x);
        FMA2(x, A2p, qz, x);
        FMA2(x, A3p, qw, x);
        ADD2(ssum2, ssum2, x);
        FMA2(ssq2, x, x, ssq2);
        float x0, x1; upk2(x0, x1, x);
        xmx = fmaxf(xmx, fmaxf(x0, x1));
        xmn = fminf(xmn, fminf(x0, x1));
    }
    float ssum, ssq;
    { float a0, a1, b0, b1; upk2(a0, a1, ssum2); upk2(b0, b1, ssq2);
      ssum = a0 + a1; ssq = b0 + b1; }
    if (npts & 1) {                        // odd tail
        int n = npair;
        float x = c;
        x = fmaf(A0, pts[g][0][n], x);
        x = fmaf(A1, pts[g][1][n], x);
        x = fmaf(A2, pts[g][2][n], x);
        x = fmaf(A3, pts[g][3][n], x);
        ssum += x; ssq = fmaf(x, x, ssq);
        xmx = fmaxf(xmx, x); xmn = fminf(xmn, x);
    }
    if (npts < NMAX) { xmx = fmaxf(xmx, 0.f); xmn = fminf(xmn, 0.f); }

    // interleaved store: [p][o>>2][ (o&3) | +4 ]
    const size_t mmb = (size_t)p * (OC*2) + (size_t)(o >> 2) * 8 + (o & 3);
    g_mm[mmb]     = xmx;
    g_mm[mmb + 4] = xmn;

    reds[tid] = ssum; redq[tid] = ssq;
    __syncthreads();
    if (tid < OC) {
        float ts = reds[tid] + reds[64+tid] + reds[128+tid] + reds[192+tid];
        float tq = redq[tid] + redq[64+tid] + redq[128+tid] + redq[192+tid];
        atomicAdd(&g_sum[tid],   ts);
        atomicAdd(&g_sumsq[tid], tq);
    }
}

// ---------------------------------------------------------------------------
// K2: finalize BN affine coefficients (1 block)
// ---------------------------------------------------------------------------
__global__ void k_bn(const float* __restrict__ gamma, const float* __restrict__ beta) {
    const int o = threadIdx.x;
    const float cnt  = (float)NPIL * (float)NMAX;
    const float mean = g_sum[o] / cnt;
    const float var  = g_sumsq[o] / cnt - mean * mean;
    const float a    = gamma[o] * rsqrtf(var + 1e-3f);
    g_a[o] = a;
    g_b[o] = beta[o] - mean * a;
}

// ---------------------------------------------------------------------------
// K3: coalesced gather-fill of the whole canvas with fused BN+ReLU+max-select.
// Thread = 4 x-cells x 4 channels. Map + mm scratch are L2-resident; output
// written with streaming stores so the 219 MB stream doesn't evict them.
// max_n relu(a*x+b) = relu(a*xmax+b) if a>=0 else relu(a*xmin+b)
// ---------------------------------------------------------------------------
__global__ __launch_bounds__(256) void k_fill(float* __restrict__ out) {
    const unsigned t  = blockIdx.x * 256u + threadIdx.x;
    const unsigned xq = t % (XL/4);                  // 108 x-quads
    const unsigned cq = (t / (XL/4)) % (OC/4);       // 16 channel-quads
    const unsigned by = t / ((XL/4) * (OC/4));       // (b,y) pair
    const unsigned b  = by / YL;
    const unsigned y  = by % YL;

    const int4 m = *(const int4*)&g_map[b * YX + y * XL + xq * 4];

    const float4 a  = *(const float4*)&g_a[cq * 4];
    const float4 bb = *(const float4*)&g_b[cq * 4];

    float4 vv[4];
    const int mi[4] = {m.x, m.y, m.z, m.w};
    #pragma unroll
    for (int i = 0; i < 4; i++) {
        if (mi[i] >= 0) {
            const float* mm = &g_mm[(size_t)mi[i] * (OC*2) + (size_t)cq * 8];
            float4 mx = *(const float4*)mm;
            float4 mn = *(const float4*)(mm + 4);
            vv[i].x = fmaxf(fmaf(a.x, (a.x >= 0.f ? mx.x : mn.x), bb.x), 0.f);
            vv[i].y = fmaxf(fmaf(a.y, (a.y >= 0.f ? mx.y : mn.y), bb.y), 0.f);
            vv[i].z = fmaxf(fmaf(a.z, (a.z >= 0.f ? mx.z : mn.z), bb.z), 0.f);
            vv[i].w = fmaxf(fmaf(a.w, (a.w >= 0.f ? mx.w : mn.w), bb.w), 0.f);
        } else {
            vv[i] = make_float4(0.f, 0.f, 0.f, 0.f);
        }
    }

    // 4x4 register transpose: plane j gets component j of each cell
    float4 w0 = make_float4(vv[0].x, vv[1].x, vv[2].x, vv[3].x);
    float4 w1 = make_float4(vv[0].y, vv[1].y, vv[2].y, vv[3].y);
    float4 w2 = make_float4(vv[0].z, vv[1].z, vv[2].z, vv[3].z);
    float4 w3 = make_float4(vv[0].w, vv[1].w, vv[2].w, vv[3].w);

    size_t base = (((size_t)b * OC + cq*4) * YL + y) * XL + xq * 4;
    __stcs((float4*)(out + base),                w0);
    __stcs((float4*)(out + base + (size_t)YX),   w1);
    __stcs((float4*)(out + base + (size_t)2*YX), w2);
    __stcs((float4*)(out + base + (size_t)3*YX), w3);
}

// ---------------------------------------------------------------------------
extern "C" void kernel_launch(void* const* d_in, const int* in_sizes, int n_in,
                              void* d_out, int out_size) {
    const float* pillars = (const float*)d_in[0];
    const int*   coors   = (const int*)  d_in[1];
    const int*   npoints = (const int*)  d_in[2];
    const float* W       = (const float*)d_in[3];
    const float* gamma   = (const float*)d_in[4];
    const float* beta    = (const float*)d_in[5];
    float* out = (float*)d_out;

    k_init  <<<(MAP_ELEMS/4 + 255) / 256, 256>>>();
    k_encode<<<NPIL / 4, 256>>>(pillars, coors, npoints, W);
    k_bn    <<<1, OC>>>(gamma, beta);
    k_fill  <<<(OUT_ELEMS/16) / 256, 256>>>(out);
}